// round 14
// baseline (speedup 1.0000x reference)
#include <cuda_runtime.h>
#include <math.h>
#include <float.h>

#define Bv 2
#define Nv 4096
#define Cv 64
#define TOPKv 24
#define MAXM 512

#define NC 10
#define NCELLS 1000
#define CELL 0.45f
#define CLO (-2.25f)

// Output layout (concatenated, float32):
// expected (B,N,3) | disp (B,3,N) | probs (B,N,N) | conf (B,N) | ent (B,N) | src_pos (B,N,3)
#define EXP_OFF   ((size_t)0)
#define DISP_OFF  ((size_t)(Bv*Nv*3))
#define PROBS_OFF ((size_t)(2*Bv*Nv*3))
#define CONF_OFF  (PROBS_OFF + (size_t)Bv*Nv*Nv)
#define ENT_OFF   (CONF_OFF + (size_t)Bv*Nv)
#define SP_OFF    (ENT_OFF + (size_t)Bv*Nv)

// Scratch (no cudaMalloc allowed)
__device__ float4 g_pack[Bv*Nv];            // (x, y, z, ||t||^2) per target node
__device__ float  g_tdT[(size_t)Bv*Nv*Cv];  // tgt_desc transposed: (B,N,64)
__device__ float  g_sdT[(size_t)Bv*Nv*Cv];  // src_desc transposed: (B,N,64)
__device__ float  g_adj[Bv*Nv];             // max(log softmax(tml)[...,0], -20) - 0.1*tgt_unc
__device__ int    g_cellcnt[Bv*NCELLS];
__device__ int    g_cellstart[Bv*(NCELLS+1)];
__device__ int    g_cellfill[Bv*NCELLS];
__device__ float4 g_cpackc[Bv*Nv];          // cell-sorted pack
__device__ int    g_cidxc[Bv*Nv];           // cell-sorted original index

__device__ __forceinline__ int cellof(float v) {
    int c = (int)floorf((v - CLO) * (1.0f / CELL));
    return min(NC - 1, max(0, c));
}

__global__ void zero_cnt_kernel() {
    int idx = blockIdx.x * blockDim.x + threadIdx.x;
    if (idx < Bv * NCELLS) g_cellcnt[idx] = 0;
}

__global__ void prep_kernel(const float* __restrict__ td,
                            const float* __restrict__ sd,
                            const float* __restrict__ tc,
                            const float* __restrict__ tml,
                            const float* __restrict__ tunc) {
    int idx = blockIdx.x * blockDim.x + threadIdx.x;
    if (idx < Bv * Cv * Nv) {
        int b = idx / (Cv * Nv);
        int r = idx - b * (Cv * Nv);
        int c = r / Nv;
        int j = r - c * Nv;
        size_t o = (((size_t)b * Nv + j) << 6) + c;
        g_tdT[o] = td[idx];
        g_sdT[o] = sd[idx];
    }
    if (idx < Bv * Nv) {
        int b = idx >> 12, j = idx & (Nv - 1);
        const float* t = tc + (size_t)b * 3 * Nv;
        float x = t[j], y = t[Nv + j], z = t[2 * Nv + j];
        g_pack[idx] = make_float4(x, y, z, x * x + y * y + z * z);
        int cell = (cellof(z) * NC + cellof(y)) * NC + cellof(x);
        atomicAdd(&g_cellcnt[b * NCELLS + cell], 1);
        float l0 = tml[(size_t)b * 2 * Nv + j];
        float l1 = tml[(size_t)b * 2 * Nv + Nv + j];
        // log(softmax[...,0]) = -log1p(exp(l1-l0)); overflow -> -inf -> clamped to -20
        g_adj[idx] = fmaxf(-log1pf(expf(l1 - l0)), -20.0f) - 0.1f * tunc[idx];
    }
}

__global__ void scan_kernel() {
    __shared__ int s[1024];
    const int b = blockIdx.x, tid = threadIdx.x;
    int v = (tid < NCELLS) ? g_cellcnt[b * NCELLS + tid] : 0;
    s[tid] = v;
    __syncthreads();
    for (int o = 1; o < 1024; o <<= 1) {
        int t = (tid >= o) ? s[tid - o] : 0;
        __syncthreads();
        s[tid] += t;
        __syncthreads();
    }
    if (tid < NCELLS) {
        int excl = s[tid] - v;
        g_cellstart[b * (NCELLS + 1) + tid] = excl;
        g_cellfill[b * NCELLS + tid] = excl;
        if (tid == NCELLS - 1) g_cellstart[b * (NCELLS + 1) + NCELLS] = s[tid];
    }
}

__global__ void scatter_kernel() {
    int idx = blockIdx.x * blockDim.x + threadIdx.x;
    if (idx >= Bv * Nv) return;
    int b = idx >> 12, j = idx & (Nv - 1);
    float4 t = g_pack[idx];
    int cell = (cellof(t.z) * NC + cellof(t.y)) * NC + cellof(t.x);
    int pos = atomicAdd(&g_cellfill[b * NCELLS + cell], 1);
    g_cpackc[(size_t)b * Nv + pos] = t;
    g_cidxc[b * Nv + pos] = j;
}

__global__ void __launch_bounds__(256, 7)
matcher_kernel(const float* __restrict__ src_can,
               const float* __restrict__ src_ml,
               const float* __restrict__ src_unc,
               float* __restrict__ out) {
    __shared__ float s_sd[64];
    __shared__ int   s_idx[MAXM];
    __shared__ float s_d2a[MAXM];
    __shared__ float s_val[MAXM];
    __shared__ float s_red[64];
    __shared__ int   s_redi[8];
    __shared__ int   s_gst[27];
    __shared__ int   s_cum[28];
    __shared__ int   s_cnt;

    const int tid  = threadIdx.x;
    const int lane = tid & 31;
    const int bi   = blockIdx.x;
    const int b    = bi >> 12;
    const int i    = bi & (Nv - 1);
    const int bN   = b * Nv;

    // Zero this row of probs output (coalesced; stores drain in background)
    float4* rowz = reinterpret_cast<float4*>(out + PROBS_OFF + (size_t)(bN + i) * Nv);
#pragma unroll
    for (int k = 0; k < 4; k++) rowz[tid + 256 * k] = make_float4(0.f, 0.f, 0.f, 0.f);

    // Source descriptor (coalesced from pre-transposed table)
    if (tid < 16)
        reinterpret_cast<float4*>(s_sd)[tid] =
            reinterpret_cast<const float4*>(g_sdT + ((size_t)(bN + i) << 6))[tid];
    if (tid == 0) s_cnt = 0;

    const float* sc = src_can + (size_t)b * 3 * Nv;
    const float sx = sc[i], sy = sc[Nv + i], sz = sc[2 * Nv + i];
    const float sn2 = sx * sx + sy * sy + sz * sz;

    const float R = 0.45f, R2 = 0.45f * 0.45f;

    // Cell window overlapping the radius ball (monotone clamped mapping ->
    // every point within R is inside these cells)
    const int cx0 = cellof(sx - R), cx1 = cellof(sx + R);
    const int cy0 = cellof(sy - R), cy1 = cellof(sy + R);
    const int cz0 = cellof(sz - R), cz1 = cellof(sz + R);
    const int nx = cx1 - cx0 + 1, ny = cy1 - cy0 + 1, nz = cz1 - cz0 + 1;
    const int ncl = nx * ny * nz;   // <= 27

    // Warp 0 builds the segment table (global start + cumulative offsets)
    if (tid < 32) {
        int seglen = 0, gstart = 0;
        if (lane < ncl) {
            int ix = lane % nx;
            int iy = (lane / nx) % ny;
            int iz = lane / (nx * ny);
            int cell = ((cz0 + iz) * NC + (cy0 + iy)) * NC + (cx0 + ix);
            const int* cs = g_cellstart + b * (NCELLS + 1);
            gstart = cs[cell];
            seglen = cs[cell + 1] - gstart;
        }
        int cum = seglen;
#pragma unroll
        for (int o = 1; o < 32; o <<= 1) {
            int t = __shfl_up_sync(0xffffffffu, cum, o);
            if (lane >= o) cum += t;
        }
        if (lane < ncl) { s_gst[lane] = gstart; s_cum[lane + 1] = cum; }
        if (lane == 0) s_cum[0] = 0;
    }
    __syncthreads();
    const int C = s_cum[ncl];

    // Fast path: scan only candidate cells (~600 points, not 4096)
    for (int q = tid; q < C; q += 256) {
        int pos = 0;
#pragma unroll
        for (int st = 16; st; st >>= 1) {
            int np = pos + st;
            if (np <= ncl - 1 && s_cum[np] <= q) pos = np;
        }
        int gpos = s_gst[pos] + (q - s_cum[pos]);
        float4 t = g_cpackc[(size_t)bN + gpos];
        float dot = fmaf(sx, t.x, fmaf(sy, t.y, sz * t.z));
        float d2 = fmaf(-2.0f, dot, sn2 + t.w);
        if (d2 <= R2) {
            int p = atomicAdd(&s_cnt, 1);
            if (p < MAXM) { s_idx[p] = g_cidxc[bN + gpos]; s_d2a[p] = d2; }
        }
    }
    __syncthreads();
    int ctot = s_cnt;

    // Rare slow path (~3%): full scan to find tau = TOPK-th smallest d2,
    // then gather extras in (R2, tau]. Recomputes d2 from g_pack.
    if (ctot < TOPKv) {
        const float4* __restrict__ pk = g_pack + bN;
        float tau = R2;
        while (ctot < TOPKv) {
            float m = FLT_MAX; int c = 0;
#pragma unroll
            for (int k = 0; k < 16; k++) {
                int j = (k << 8) + tid;
                float4 t = pk[j];
                float dot = fmaf(sx, t.x, fmaf(sy, t.y, sz * t.z));
                float d2 = fmaf(-2.0f, dot, sn2 + t.w);
                if (d2 > tau) {
                    if (d2 < m) { m = d2; c = 1; }
                    else if (d2 == m) c++;
                }
            }
#pragma unroll
            for (int o = 16; o; o >>= 1) {
                float om = __shfl_xor_sync(0xffffffffu, m, o);
                int   oc = __shfl_xor_sync(0xffffffffu, c, o);
                if (om < m) { m = om; c = oc; }
                else if (om == m) c += oc;
            }
            if (lane == 0) { s_red[tid >> 5] = m; s_redi[tid >> 5] = c; }
            __syncthreads();
            float mm = s_red[0]; int cc = s_redi[0];
#pragma unroll
            for (int w = 1; w < 8; w++) {
                if (s_red[w] < mm) { mm = s_red[w]; cc = s_redi[w]; }
                else if (s_red[w] == mm) cc += s_redi[w];
            }
            __syncthreads();
            if (mm >= FLT_MAX) break;
            tau = mm; ctot += cc;
        }
#pragma unroll
        for (int k = 0; k < 16; k++) {
            int j = (k << 8) + tid;
            float4 t = pk[j];
            float dot = fmaf(sx, t.x, fmaf(sy, t.y, sz * t.z));
            float d2 = fmaf(-2.0f, dot, sn2 + t.w);
            if (d2 > R2 && d2 <= tau) {
                int p = atomicAdd(&s_cnt, 1);
                if (p < MAXM) { s_idx[p] = j; s_d2a[p] = d2; }
            }
        }
        __syncthreads();
    }
    const int M = min(s_cnt, MAXM);

    // Scores: half-warp (16 lanes) per pair, float4 loads, 4 shuffles/pair.
    // Block-uniform trip count -> every lane executes every shuffle (safe).
    const float sunc = src_unc[bN + i];
    {
        const int half = tid >> 4;        // 0..15
        const int hl   = tid & 15;
        const float4 sd4 = reinterpret_cast<const float4*>(s_sd)[hl];
        const int T = (M + 15) >> 4;
        for (int t = 0; t < T; t++) {
            int p = (t << 4) + half;
            float part = 0.0f;
            int j = 0;
            if (p < M) {
                j = s_idx[p];
                float4 v = reinterpret_cast<const float4*>(
                               g_tdT + ((size_t)(bN + j) << 6))[hl];
                part = fmaf(v.x, sd4.x, fmaf(v.y, sd4.y,
                       fmaf(v.z, sd4.z, v.w * sd4.w)));
            }
#pragma unroll
            for (int o = 8; o; o >>= 1)
                part += __shfl_xor_sync(0xffffffffu, part, o, 16);
            if (hl == 0 && p < M) {
                float dist = sqrtf(fmaxf(s_d2a[p], 1e-12f));
                s_val[p] = part - dist - 0.1f * sunc + g_adj[bN + j];
            }
        }
    }
    __syncthreads();

    // Softmax over the sparse allowed set (disallowed entries underflow to exact 0
    // in the reference as well: exp(-1e4/0.07) == 0 in fp32)
    // Round 1: block max
    float lm = -FLT_MAX;
    for (int p = tid; p < M; p += 256) lm = fmaxf(lm, s_val[p]);
#pragma unroll
    for (int o = 16; o; o >>= 1) lm = fmaxf(lm, __shfl_xor_sync(0xffffffffu, lm, o));
    if (lane == 0) s_red[56 + (tid >> 5)] = lm;
    __syncthreads();
    float mx = s_red[56];
#pragma unroll
    for (int w = 1; w < 8; w++) mx = fmaxf(mx, s_red[56 + w]);

    // Round 2: one fused round for (Z, eu, e0, e1, e2, em)
    const float invT = 1.0f / 0.07f;
    const float step = 2.0f / 15.0f;
    float Z = 0.f, eu = 0.f, e0 = 0.f, e1 = 0.f, e2 = 0.f, em = 0.f;
    for (int p = tid; p < M; p += 256) {
        float u = (s_val[p] - mx) * invT;
        float e = __expf(u);
        s_val[p] = e;
        Z += e; eu += e * u; em = fmaxf(em, e);
        int j = s_idx[p];
        float c0 = (float)(j >> 8) * step - 1.0f;
        float c1 = (float)((j >> 4) & 15) * step - 1.0f;
        float c2 = (float)(j & 15) * step - 1.0f;
        e0 += e * c0; e1 += e * c1; e2 += e * c2;
    }
#pragma unroll
    for (int o = 16; o; o >>= 1) {
        Z  += __shfl_xor_sync(0xffffffffu, Z, o);
        eu += __shfl_xor_sync(0xffffffffu, eu, o);
        e0 += __shfl_xor_sync(0xffffffffu, e0, o);
        e1 += __shfl_xor_sync(0xffffffffu, e1, o);
        e2 += __shfl_xor_sync(0xffffffffu, e2, o);
        em  = fmaxf(em, __shfl_xor_sync(0xffffffffu, em, o));
    }
    if (lane == 0) {
        int base = (tid >> 5) * 6;               // [0..47], disjoint from [56..63]
        s_red[base + 0] = Z;  s_red[base + 1] = eu; s_red[base + 2] = e0;
        s_red[base + 3] = e1; s_red[base + 4] = e2; s_red[base + 5] = em;
    }
    __syncthreads();
    // lanes 0..5 of every warp each reduce one quantity over the 8 warps
    float acc = 0.f;
    if (lane < 5) {
#pragma unroll
        for (int w = 0; w < 8; w++) acc += s_red[w * 6 + lane];
    } else if (lane == 5) {
        acc = s_red[5];
#pragma unroll
        for (int w = 1; w < 8; w++) acc = fmaxf(acc, s_red[w * 6 + 5]);
    }
    float rZ  = __shfl_sync(0xffffffffu, acc, 0);
    float reu = __shfl_sync(0xffffffffu, acc, 1);
    float re0 = __shfl_sync(0xffffffffu, acc, 2);
    float re1 = __shfl_sync(0xffffffffu, acc, 3);
    float re2 = __shfl_sync(0xffffffffu, acc, 4);
    float rem = __shfl_sync(0xffffffffu, acc, 5);

    float invZ = 1.0f / rZ;

    // Direct sparse scatter (row already zeroed)
    float* rowp = out + PROBS_OFF + (size_t)(bN + i) * Nv;
    for (int p = tid; p < M; p += 256) rowp[s_idx[p]] = s_val[p] * invZ;

    if (tid == 0) {
        float Ex0 = re0 * invZ, Ex1 = re1 * invZ, Ex2 = re2 * invZ;
        float p0 = (float)(i >> 8) * step - 1.0f;
        float p1 = (float)((i >> 4) & 15) * step - 1.0f;
        float p2 = (float)(i & 15) * step - 1.0f;
        size_t ri = (size_t)(bN + i);
        out[EXP_OFF + ri * 3 + 0] = Ex0;
        out[EXP_OFF + ri * 3 + 1] = Ex1;
        out[EXP_OFF + ri * 3 + 2] = Ex2;
        out[DISP_OFF + (size_t)b * 3 * Nv + 0 * Nv + i] = Ex0 - p0;
        out[DISP_OFF + (size_t)b * 3 * Nv + 1 * Nv + i] = Ex1 - p1;
        out[DISP_OFF + (size_t)b * 3 * Nv + 2 * Nv + i] = Ex2 - p2;
        float l0 = src_ml[(size_t)b * 2 * Nv + i];
        float l1 = src_ml[(size_t)b * 2 * Nv + Nv + i];
        float smatch = 1.0f / (1.0f + __expf(l1 - l0));
        out[CONF_OFF + ri] = rem * invZ * smatch;
        // ent = -sum p log p = logZ - (sum e*u)/Z   with u = (s - max)/T
        out[ENT_OFF + ri] = __logf(rZ) - reu * invZ;
        out[SP_OFF + ri * 3 + 0] = p0;
        out[SP_OFF + ri * 3 + 1] = p1;
        out[SP_OFF + ri * 3 + 2] = p2;
    }
}

extern "C" void kernel_launch(void* const* d_in, const int* in_sizes, int n_in,
                              void* d_out, int out_size) {
    const float* src_can  = (const float*)d_in[0];
    const float* tgt_can  = (const float*)d_in[1];
    const float* src_desc = (const float*)d_in[2];
    const float* tgt_desc = (const float*)d_in[3];
    const float* src_ml   = (const float*)d_in[4];
    const float* tgt_ml   = (const float*)d_in[5];
    const float* src_unc  = (const float*)d_in[6];
    const float* tgt_unc  = (const float*)d_in[7];
    float* out = (float*)d_out;

    zero_cnt_kernel<<<(Bv * NCELLS + 255) / 256, 256>>>();
    prep_kernel<<<(Bv * Cv * Nv + 255) / 256, 256>>>(tgt_desc, src_desc, tgt_can,
                                                     tgt_ml, tgt_unc);
    scan_kernel<<<Bv, 1024>>>();
    scatter_kernel<<<(Bv * Nv + 255) / 256, 256>>>();
    matcher_kernel<<<Bv * Nv, 256>>>(src_can, src_ml, src_unc, out);
}

// round 15
// speedup vs baseline: 2.6722x; 2.6722x over previous
#include <cuda_runtime.h>
#include <math.h>
#include <float.h>

#define Bv 2
#define Nv 4096
#define Cv 64
#define TOPKv 24
#define MAXM 512

// Output layout (concatenated, float32):
// expected (B,N,3) | disp (B,3,N) | probs (B,N,N) | conf (B,N) | ent (B,N) | src_pos (B,N,3)
#define EXP_OFF   ((size_t)0)
#define DISP_OFF  ((size_t)(Bv*Nv*3))
#define PROBS_OFF ((size_t)(2*Bv*Nv*3))
#define CONF_OFF  (PROBS_OFF + (size_t)Bv*Nv*Nv)
#define ENT_OFF   (CONF_OFF + (size_t)Bv*Nv)
#define SP_OFF    (ENT_OFF + (size_t)Bv*Nv)

// Scratch (no cudaMalloc allowed)
__device__ float4 g_pack[Bv*Nv];            // (x, y, z, ||t||^2) per target node
__device__ float  g_tdT[(size_t)Bv*Nv*Cv];  // tgt_desc transposed: (B,N,64)
__device__ float  g_sdT[(size_t)Bv*Nv*Cv];  // src_desc transposed: (B,N,64)
__device__ float  g_adj[Bv*Nv];             // max(log softmax(tml)[...,0], -20) - 0.1*tgt_unc

// Coalesced 32x32 tiled transpose: (B,64,N) -> (B,N,64) for both desc tensors
__global__ void transpose_kernel(const float* __restrict__ td,
                                 const float* __restrict__ sd) {
    __shared__ float tile[32][33];
    const int jb = blockIdx.x * 32;      // Nv/32 tiles
    const int cb = blockIdx.y * 32;      // Cv/32 tiles
    const int zz = blockIdx.z;           // b*2 + which
    const int b  = zz >> 1;
    const float* src = (zz & 1) ? sd : td;
    float* dst       = (zz & 1) ? g_sdT : g_tdT;
    const int tx = threadIdx.x, ty = threadIdx.y;   // 32 x 8
    const float* s = src + (size_t)b * Cv * Nv;
#pragma unroll
    for (int k = 0; k < 4; k++)
        tile[ty + k * 8][tx] = s[(size_t)(cb + ty + k * 8) * Nv + jb + tx];
    __syncthreads();
    float* d = dst + (size_t)b * Nv * 64;
#pragma unroll
    for (int k = 0; k < 4; k++)
        d[(size_t)(jb + ty + k * 8) * 64 + cb + tx] = tile[tx][ty + k * 8];
}

__global__ void prep_kernel(const float* __restrict__ tc,
                            const float* __restrict__ tml,
                            const float* __restrict__ tunc) {
    int idx = blockIdx.x * blockDim.x + threadIdx.x;
    if (idx < Bv * Nv) {
        int b = idx >> 12, j = idx & (Nv - 1);
        const float* t = tc + (size_t)b * 3 * Nv;
        float x = t[j], y = t[Nv + j], z = t[2 * Nv + j];
        g_pack[idx] = make_float4(x, y, z, x * x + y * y + z * z);
        float l0 = tml[(size_t)b * 2 * Nv + j];
        float l1 = tml[(size_t)b * 2 * Nv + Nv + j];
        // log(softmax[...,0]) = -log1p(exp(l1-l0)); overflow -> -inf -> clamped to -20
        g_adj[idx] = fmaxf(-log1pf(expf(l1 - l0)), -20.0f) - 0.1f * tunc[idx];
    }
}

__global__ void __launch_bounds__(256, 7)
matcher_kernel(const float* __restrict__ src_can,
               const float* __restrict__ src_ml,
               const float* __restrict__ src_unc,
               float* __restrict__ out) {
    __shared__ float s_d2[Nv];            // 16 KB: all squared distances
    __shared__ float s_sd[64];
    __shared__ int   s_idx[MAXM];
    __shared__ float s_val[MAXM];         // selection candidates, then score, then exp
    __shared__ float s_red[64];
    __shared__ int   s_redi[8];
    __shared__ int   s_hist[256];         // exponent-byte histogram (slow path)
    __shared__ int   s_binB, s_kb, s_c2;
    __shared__ float s_tau;
    __shared__ int   s_cnt;

    const int tid  = threadIdx.x;
    const int lane = tid & 31;
    const int bi   = blockIdx.x;
    const int b    = bi >> 12;
    const int i    = bi & (Nv - 1);
    const int bN   = b * Nv;

    // Zero this row of probs output (coalesced; stores drain in background)
    float4* rowz = reinterpret_cast<float4*>(out + PROBS_OFF + (size_t)(bN + i) * Nv);
#pragma unroll
    for (int k = 0; k < 4; k++) rowz[tid + 256 * k] = make_float4(0.f, 0.f, 0.f, 0.f);

    // Source descriptor (coalesced from pre-transposed table)
    if (tid < 16)
        reinterpret_cast<float4*>(s_sd)[tid] =
            reinterpret_cast<const float4*>(g_sdT + ((size_t)(bN + i) << 6))[tid];
    if (tid == 0) s_cnt = 0;

    const float* sc = src_can + (size_t)b * 3 * Nv;
    const float sx = sc[i], sy = sc[Nv + i], sz = sc[2 * Nv + i];
    const float sn2 = sx * sx + sy * sy + sz * sz;

    const float4* __restrict__ pk = g_pack + bN;
    const float R2 = 0.45f * 0.45f;

    __syncthreads();   // s_cnt init visible before gather atomics

    // Pass 1: all 4096 squared distances -> smem, radius hits -> register bitmask.
    // Pure LDG.128 / FMA / STS / predicated-OR stream (MLP preserved).
    unsigned hm = 0;
#pragma unroll
    for (int k = 0; k < 16; k++) {
        int j = (k << 8) + tid;
        float4 t = pk[j];
        float dot = fmaf(sx, t.x, fmaf(sy, t.y, sz * t.z));
        float d2 = fmaf(-2.0f, dot, sn2 + t.w);
        s_d2[j] = d2;
        if (d2 <= R2) hm |= (1u << k);
    }

    // Gather: only threads owning hits (~30 per block) touch the atomic.
    if (hm) {
        int base = atomicAdd(&s_cnt, __popc(hm));
        while (hm) {
            int k = __ffs(hm) - 1;
            hm &= hm - 1;
            if (base < MAXM) s_idx[base] = (k << 8) + tid;
            base++;
        }
    }
    __syncthreads();
    int ctot = s_cnt;

    // Slow path (~40% of rows!): find tau = TOPK-th smallest d2 via one-shot
    // exponent-histogram select (replaces one-element-per-iteration extraction).
    if (ctot < TOPKv) {
        s_hist[tid] = 0;
        __syncthreads();
        // histogram of exponent byte; float bits are monotone for values >= 0
#pragma unroll
        for (int k = 0; k < 16; k++) {
            unsigned bits = __float_as_uint(fmaxf(s_d2[(k << 8) + tid], 0.0f));
            atomicAdd(&s_hist[bits >> 23], 1);
        }
        __syncthreads();
        // block inclusive scan over 256 bins (one per thread)
        int v = s_hist[tid];
        int cum = v;
#pragma unroll
        for (int o = 1; o < 32; o <<= 1) {
            int t = __shfl_up_sync(0xffffffffu, cum, o);
            if (lane >= o) cum += t;
        }
        if (lane == 31) s_redi[tid >> 5] = cum;
        __syncthreads();
        int off = 0;
        for (int w = 0; w < (tid >> 5); w++) off += s_redi[w];
        cum += off;
        // unique crossing bin: first bin with cum >= TOPK
        if (cum >= TOPKv && cum - v < TOPKv) { s_binB = tid; s_kb = cum - v; }
        if (tid == 0) s_c2 = 0;
        __syncthreads();
        const int B = s_binB;
        const int r = TOPKv - s_kb;      // r-th smallest within bin B (1-indexed)
        // gather bin-B candidate values (log-spaced bins near the 24th-smallest
        // quantile hold <= ~70 values for this data)
#pragma unroll
        for (int k = 0; k < 16; k++) {
            float key = fmaxf(s_d2[(k << 8) + tid], 0.0f);
            if ((int)(__float_as_uint(key) >> 23) == B) {
                int p = atomicAdd(&s_c2, 1);
                if (p < MAXM) s_val[p] = key;
            }
        }
        __syncthreads();
        int c2 = min(s_c2, MAXM);
        // exact rank within bin: tau = value with strict-rank <= r-1 < rank+eq
        for (int p = tid; p < c2; p += 256) {
            float x = s_val[p];
            int lt = 0, eq = 0;
            for (int q = 0; q < c2; q++) {
                float y = s_val[q];
                lt += (y < x);
                eq += (y == x);
            }
            if (lt <= r - 1 && r - 1 < lt + eq) s_tau = x;
        }
        __syncthreads();
        const float tau = s_tau;
        // gather extras in (R2, tau]
#pragma unroll
        for (int k = 0; k < 16; k++) {
            int j = (k << 8) + tid;
            float d2 = s_d2[j];
            if (d2 > R2 && fmaxf(d2, 0.0f) <= tau) {
                int p = atomicAdd(&s_cnt, 1);
                if (p < MAXM) s_idx[p] = j;
            }
        }
        __syncthreads();
    }
    const int M = min(s_cnt, MAXM);

    // Scores: half-warp (16 lanes) per pair, float4 loads, 4 shuffles/pair.
    // Block-uniform trip count -> every lane executes every shuffle (safe).
    const float sunc = src_unc[bN + i];
    {
        const int half = tid >> 4;        // 0..15
        const int hl   = tid & 15;
        const float4 sd4 = reinterpret_cast<const float4*>(s_sd)[hl];
        const int T = (M + 15) >> 4;
        for (int t = 0; t < T; t++) {
            int p = (t << 4) + half;
            float part = 0.0f;
            int j = 0;
            if (p < M) {
                j = s_idx[p];
                float4 v = reinterpret_cast<const float4*>(
                               g_tdT + ((size_t)(bN + j) << 6))[hl];
                part = fmaf(v.x, sd4.x, fmaf(v.y, sd4.y,
                       fmaf(v.z, sd4.z, v.w * sd4.w)));
            }
#pragma unroll
            for (int o = 8; o; o >>= 1)
                part += __shfl_xor_sync(0xffffffffu, part, o, 16);
            if (hl == 0 && p < M) {
                float dist = sqrtf(fmaxf(s_d2[j], 1e-12f));
                s_val[p] = part - dist - 0.1f * sunc + g_adj[bN + j];
            }
        }
    }
    __syncthreads();

    // Softmax over the sparse allowed set (disallowed entries underflow to exact 0
    // in the reference as well: exp(-1e4/0.07) == 0 in fp32)
    // Round 1: block max
    float lm = -FLT_MAX;
    for (int p = tid; p < M; p += 256) lm = fmaxf(lm, s_val[p]);
#pragma unroll
    for (int o = 16; o; o >>= 1) lm = fmaxf(lm, __shfl_xor_sync(0xffffffffu, lm, o));
    if (lane == 0) s_red[56 + (tid >> 5)] = lm;
    __syncthreads();
    float mx = s_red[56];
#pragma unroll
    for (int w = 1; w < 8; w++) mx = fmaxf(mx, s_red[56 + w]);

    // Round 2: one fused round for (Z, eu, e0, e1, e2, em)
    const float invT = 1.0f / 0.07f;
    const float step = 2.0f / 15.0f;
    float Z = 0.f, eu = 0.f, e0 = 0.f, e1 = 0.f, e2 = 0.f, em = 0.f;
    for (int p = tid; p < M; p += 256) {
        float u = (s_val[p] - mx) * invT;
        float e = __expf(u);
        s_val[p] = e;
        Z += e; eu += e * u; em = fmaxf(em, e);
        int j = s_idx[p];
        float c0 = (float)(j >> 8) * step - 1.0f;
        float c1 = (float)((j >> 4) & 15) * step - 1.0f;
        float c2 = (float)(j & 15) * step - 1.0f;
        e0 += e * c0; e1 += e * c1; e2 += e * c2;
    }
#pragma unroll
    for (int o = 16; o; o >>= 1) {
        Z  += __shfl_xor_sync(0xffffffffu, Z, o);
        eu += __shfl_xor_sync(0xffffffffu, eu, o);
        e0 += __shfl_xor_sync(0xffffffffu, e0, o);
        e1 += __shfl_xor_sync(0xffffffffu, e1, o);
        e2 += __shfl_xor_sync(0xffffffffu, e2, o);
        em  = fmaxf(em, __shfl_xor_sync(0xffffffffu, em, o));
    }
    if (lane == 0) {
        int base = (tid >> 5) * 6;               // [0..47], disjoint from [56..63]
        s_red[base + 0] = Z;  s_red[base + 1] = eu; s_red[base + 2] = e0;
        s_red[base + 3] = e1; s_red[base + 4] = e2; s_red[base + 5] = em;
    }
    __syncthreads();
    // lanes 0..5 of every warp each reduce one quantity over the 8 warps
    float acc = 0.f;
    if (lane < 5) {
#pragma unroll
        for (int w = 0; w < 8; w++) acc += s_red[w * 6 + lane];
    } else if (lane == 5) {
        acc = s_red[5];
#pragma unroll
        for (int w = 1; w < 8; w++) acc = fmaxf(acc, s_red[w * 6 + 5]);
    }
    float rZ  = __shfl_sync(0xffffffffu, acc, 0);
    float reu = __shfl_sync(0xffffffffu, acc, 1);
    float re0 = __shfl_sync(0xffffffffu, acc, 2);
    float re1 = __shfl_sync(0xffffffffu, acc, 3);
    float re2 = __shfl_sync(0xffffffffu, acc, 4);
    float rem = __shfl_sync(0xffffffffu, acc, 5);

    float invZ = 1.0f / rZ;

    // Direct sparse scatter (row already zeroed)
    float* rowp = out + PROBS_OFF + (size_t)(bN + i) * Nv;
    for (int p = tid; p < M; p += 256) rowp[s_idx[p]] = s_val[p] * invZ;

    if (tid == 0) {
        float Ex0 = re0 * invZ, Ex1 = re1 * invZ, Ex2 = re2 * invZ;
        float p0 = (float)(i >> 8) * step - 1.0f;
        float p1 = (float)((i >> 4) & 15) * step - 1.0f;
        float p2 = (float)(i & 15) * step - 1.0f;
        size_t ri = (size_t)(bN + i);
        out[EXP_OFF + ri * 3 + 0] = Ex0;
        out[EXP_OFF + ri * 3 + 1] = Ex1;
        out[EXP_OFF + ri * 3 + 2] = Ex2;
        out[DISP_OFF + (size_t)b * 3 * Nv + 0 * Nv + i] = Ex0 - p0;
        out[DISP_OFF + (size_t)b * 3 * Nv + 1 * Nv + i] = Ex1 - p1;
        out[DISP_OFF + (size_t)b * 3 * Nv + 2 * Nv + i] = Ex2 - p2;
        float l0 = src_ml[(size_t)b * 2 * Nv + i];
        float l1 = src_ml[(size_t)b * 2 * Nv + Nv + i];
        float smatch = 1.0f / (1.0f + __expf(l1 - l0));
        out[CONF_OFF + ri] = rem * invZ * smatch;
        // ent = -sum p log p = logZ - (sum e*u)/Z   with u = (s - max)/T
        out[ENT_OFF + ri] = __logf(rZ) - reu * invZ;
        out[SP_OFF + ri * 3 + 0] = p0;
        out[SP_OFF + ri * 3 + 1] = p1;
        out[SP_OFF + ri * 3 + 2] = p2;
    }
}

extern "C" void kernel_launch(void* const* d_in, const int* in_sizes, int n_in,
                              void* d_out, int out_size) {
    const float* src_can  = (const float*)d_in[0];
    const float* tgt_can  = (const float*)d_in[1];
    const float* src_desc = (const float*)d_in[2];
    const float* tgt_desc = (const float*)d_in[3];
    const float* src_ml   = (const float*)d_in[4];
    const float* tgt_ml   = (const float*)d_in[5];
    const float* src_unc  = (const float*)d_in[6];
    const float* tgt_unc  = (const float*)d_in[7];
    float* out = (float*)d_out;

    dim3 tgrid(Nv / 32, Cv / 32, Bv * 2);
    dim3 tblk(32, 8);
    transpose_kernel<<<tgrid, tblk>>>(tgt_desc, src_desc);
    prep_kernel<<<(Bv * Nv + 255) / 256, 256>>>(tgt_can, tgt_ml, tgt_unc);
    matcher_kernel<<<Bv * Nv, 256>>>(src_can, src_ml, src_unc, out);
}

// round 16
// speedup vs baseline: 2.9721x; 1.1122x over previous
#include <cuda_runtime.h>
#include <math.h>
#include <float.h>

#define Bv 2
#define Nv 4096
#define Cv 64
#define TOPKv 24
#define MAXM 512

// Output layout (concatenated, float32):
// expected (B,N,3) | disp (B,3,N) | probs (B,N,N) | conf (B,N) | ent (B,N) | src_pos (B,N,3)
#define EXP_OFF   ((size_t)0)
#define DISP_OFF  ((size_t)(Bv*Nv*3))
#define PROBS_OFF ((size_t)(2*Bv*Nv*3))
#define CONF_OFF  (PROBS_OFF + (size_t)Bv*Nv*Nv)
#define ENT_OFF   (CONF_OFF + (size_t)Bv*Nv)
#define SP_OFF    (ENT_OFF + (size_t)Bv*Nv)

// Scratch (no cudaMalloc allowed)
__device__ float4 g_pack[Bv*Nv];            // (x, y, z, ||t||^2) per target node
__device__ float  g_tdT[(size_t)Bv*Nv*Cv];  // tgt_desc transposed: (B,N,64)
__device__ float  g_sdT[(size_t)Bv*Nv*Cv];  // src_desc transposed: (B,N,64)
__device__ float  g_adj[Bv*Nv];             // max(log softmax(tml)[...,0], -20) - 0.1*tgt_unc

// Coalesced 32x32 tiled transpose: (B,64,N) -> (B,N,64) for both desc tensors
__global__ void transpose_kernel(const float* __restrict__ td,
                                 const float* __restrict__ sd) {
    __shared__ float tile[32][33];
    const int jb = blockIdx.x * 32;      // Nv/32 tiles
    const int cb = blockIdx.y * 32;      // Cv/32 tiles
    const int zz = blockIdx.z;           // b*2 + which
    const int b  = zz >> 1;
    const float* src = (zz & 1) ? sd : td;
    float* dst       = (zz & 1) ? g_sdT : g_tdT;
    const int tx = threadIdx.x, ty = threadIdx.y;   // 32 x 8
    const float* s = src + (size_t)b * Cv * Nv;
#pragma unroll
    for (int k = 0; k < 4; k++)
        tile[ty + k * 8][tx] = s[(size_t)(cb + ty + k * 8) * Nv + jb + tx];
    __syncthreads();
    float* d = dst + (size_t)b * Nv * 64;
#pragma unroll
    for (int k = 0; k < 4; k++)
        d[(size_t)(jb + ty + k * 8) * 64 + cb + tx] = tile[tx][ty + k * 8];
}

__global__ void prep_kernel(const float* __restrict__ tc,
                            const float* __restrict__ tml,
                            const float* __restrict__ tunc) {
    int idx = blockIdx.x * blockDim.x + threadIdx.x;
    if (idx < Bv * Nv) {
        int b = idx >> 12, j = idx & (Nv - 1);
        const float* t = tc + (size_t)b * 3 * Nv;
        float x = t[j], y = t[Nv + j], z = t[2 * Nv + j];
        g_pack[idx] = make_float4(x, y, z, x * x + y * y + z * z);
        float l0 = tml[(size_t)b * 2 * Nv + j];
        float l1 = tml[(size_t)b * 2 * Nv + Nv + j];
        // log(softmax[...,0]) = -log1p(exp(l1-l0)); overflow -> -inf -> clamped to -20
        g_adj[idx] = fmaxf(-log1pf(expf(l1 - l0)), -20.0f) - 0.1f * tunc[idx];
    }
}

__global__ void __launch_bounds__(256, 7)
matcher_kernel(const float* __restrict__ src_can,
               const float* __restrict__ src_ml,
               const float* __restrict__ src_unc,
               float* __restrict__ out) {
    __shared__ float s_d2[Nv];            // 16 KB: all squared distances
    __shared__ float s_sd[64];
    __shared__ int   s_idx[MAXM];
    __shared__ float s_val[MAXM];         // selection candidates, then score, then exp
    __shared__ int   s_redi[8];
    __shared__ int   s_hist[256];         // exponent-byte histogram (slow path)
    __shared__ int   s_binB, s_kb, s_c2;
    __shared__ float s_tau;
    __shared__ int   s_cnt;

    const int tid  = threadIdx.x;
    const int lane = tid & 31;
    const int bi   = blockIdx.x;
    const int b    = bi >> 12;
    const int i    = bi & (Nv - 1);
    const int bN   = b * Nv;

    // Zero this row of probs output (coalesced; stores drain in background)
    float4* rowz = reinterpret_cast<float4*>(out + PROBS_OFF + (size_t)(bN + i) * Nv);
#pragma unroll
    for (int k = 0; k < 4; k++) rowz[tid + 256 * k] = make_float4(0.f, 0.f, 0.f, 0.f);

    // Source descriptor (coalesced from pre-transposed table)
    if (tid < 16)
        reinterpret_cast<float4*>(s_sd)[tid] =
            reinterpret_cast<const float4*>(g_sdT + ((size_t)(bN + i) << 6))[tid];
    if (tid == 0) s_cnt = 0;

    const float* sc = src_can + (size_t)b * 3 * Nv;
    const float sx = sc[i], sy = sc[Nv + i], sz = sc[2 * Nv + i];
    const float sn2 = sx * sx + sy * sy + sz * sz;

    const float4* __restrict__ pk = g_pack + bN;
    const float R2 = 0.45f * 0.45f;

    __syncthreads();   // s_cnt init visible before gather atomics

    // Pass 1: all 4096 squared distances -> smem, radius hits -> register bitmask.
    // Pure LDG.128 / FMA / STS / predicated-OR stream (MLP preserved).
    unsigned hm = 0;
#pragma unroll
    for (int k = 0; k < 16; k++) {
        int j = (k << 8) + tid;
        float4 t = pk[j];
        float dot = fmaf(sx, t.x, fmaf(sy, t.y, sz * t.z));
        float d2 = fmaf(-2.0f, dot, sn2 + t.w);
        s_d2[j] = d2;
        if (d2 <= R2) hm |= (1u << k);
    }

    // Gather: only threads owning hits (~30 per block) touch the atomic.
    if (hm) {
        int base = atomicAdd(&s_cnt, __popc(hm));
        while (hm) {
            int k = __ffs(hm) - 1;
            hm &= hm - 1;
            if (base < MAXM) s_idx[base] = (k << 8) + tid;
            base++;
        }
    }
    __syncthreads();
    int ctot = s_cnt;

    // Slow path (~40% of rows): find tau = TOPK-th smallest d2 via one-shot
    // exponent-histogram select (validated in R15).
    if (ctot < TOPKv) {
        s_hist[tid] = 0;
        __syncthreads();
        // histogram of exponent byte; float bits are monotone for values >= 0
#pragma unroll
        for (int k = 0; k < 16; k++) {
            unsigned bits = __float_as_uint(fmaxf(s_d2[(k << 8) + tid], 0.0f));
            atomicAdd(&s_hist[bits >> 23], 1);
        }
        __syncthreads();
        // block inclusive scan over 256 bins (one per thread)
        int v = s_hist[tid];
        int cum = v;
#pragma unroll
        for (int o = 1; o < 32; o <<= 1) {
            int t = __shfl_up_sync(0xffffffffu, cum, o);
            if (lane >= o) cum += t;
        }
        if (lane == 31) s_redi[tid >> 5] = cum;
        __syncthreads();
        int off = 0;
        for (int w = 0; w < (tid >> 5); w++) off += s_redi[w];
        cum += off;
        // unique crossing bin: first bin with cum >= TOPK
        if (cum >= TOPKv && cum - v < TOPKv) { s_binB = tid; s_kb = cum - v; }
        if (tid == 0) s_c2 = 0;
        __syncthreads();
        const int B = s_binB;
        const int r = TOPKv - s_kb;      // r-th smallest within bin B (1-indexed)
        // gather bin-B candidate values
#pragma unroll
        for (int k = 0; k < 16; k++) {
            float key = fmaxf(s_d2[(k << 8) + tid], 0.0f);
            if ((int)(__float_as_uint(key) >> 23) == B) {
                int p = atomicAdd(&s_c2, 1);
                if (p < MAXM) s_val[p] = key;
            }
        }
        __syncthreads();
        int c2 = min(s_c2, MAXM);
        // exact rank within bin: tau = value with strict-rank <= r-1 < rank+eq
        for (int p = tid; p < c2; p += 256) {
            float x = s_val[p];
            int lt = 0, eq = 0;
            for (int q = 0; q < c2; q++) {
                float y = s_val[q];
                lt += (y < x);
                eq += (y == x);
            }
            if (lt <= r - 1 && r - 1 < lt + eq) s_tau = x;
        }
        __syncthreads();
        const float tau = s_tau;
        // gather extras in (R2, tau]
#pragma unroll
        for (int k = 0; k < 16; k++) {
            int j = (k << 8) + tid;
            float d2 = s_d2[j];
            if (d2 > R2 && fmaxf(d2, 0.0f) <= tau) {
                int p = atomicAdd(&s_cnt, 1);
                if (p < MAXM) s_idx[p] = j;
            }
        }
        __syncthreads();
    }
    const int M = min(s_cnt, MAXM);

    // Scores: half-warp (16 lanes) per pair, float4 loads, 4 shuffles/pair.
    // Block-uniform trip count -> every lane executes every shuffle (safe).
    const float sunc = src_unc[bN + i];
    {
        const int half = tid >> 4;        // 0..15
        const int hl   = tid & 15;
        const float4 sd4 = reinterpret_cast<const float4*>(s_sd)[hl];
        const int T = (M + 15) >> 4;
        for (int t = 0; t < T; t++) {
            int p = (t << 4) + half;
            float part = 0.0f;
            int j = 0;
            if (p < M) {
                j = s_idx[p];
                float4 v = reinterpret_cast<const float4*>(
                               g_tdT + ((size_t)(bN + j) << 6))[hl];
                part = fmaf(v.x, sd4.x, fmaf(v.y, sd4.y,
                       fmaf(v.z, sd4.z, v.w * sd4.w)));
            }
#pragma unroll
            for (int o = 8; o; o >>= 1)
                part += __shfl_xor_sync(0xffffffffu, part, o, 16);
            if (hl == 0 && p < M) {
                float dist = sqrtf(fmaxf(s_d2[j], 1e-12f));
                s_val[p] = part - dist - 0.1f * sunc + g_adj[bN + j];
            }
        }
    }
    __syncthreads();   // s_val/s_idx complete and visible

    // ── Warp-specialized tail: warps 1..7 exit; warp 0 owns the softmax,
    //    scatter, and epilogue (M ~ 35 fits one warp; no barriers needed). ──
    if (tid >= 32) return;

    // Max over scores (32-lane strided + shuffle reduce)
    float lm = -FLT_MAX;
    for (int p = lane; p < M; p += 32) lm = fmaxf(lm, s_val[p]);
#pragma unroll
    for (int o = 16; o; o >>= 1) lm = fmaxf(lm, __shfl_xor_sync(0xffffffffu, lm, o));
    const float mx = lm;

    // Fused sums (Z, eu, e0, e1, e2). Note max prob = exp(0)/Z = 1/Z exactly,
    // so no 'em' reduction is needed: conf = (1/Z) * smatch.
    const float invT = 1.0f / 0.07f;
    const float step = 2.0f / 15.0f;
    float Z = 0.f, eu = 0.f, e0 = 0.f, e1 = 0.f, e2 = 0.f;
    for (int p = lane; p < M; p += 32) {
        float u = (s_val[p] - mx) * invT;
        float e = __expf(u);
        s_val[p] = e;
        Z += e; eu += e * u;
        int j = s_idx[p];
        float c0 = (float)(j >> 8) * step - 1.0f;
        float c1 = (float)((j >> 4) & 15) * step - 1.0f;
        float c2 = (float)(j & 15) * step - 1.0f;
        e0 += e * c0; e1 += e * c1; e2 += e * c2;
    }
#pragma unroll
    for (int o = 16; o; o >>= 1) {
        Z  += __shfl_xor_sync(0xffffffffu, Z, o);
        eu += __shfl_xor_sync(0xffffffffu, eu, o);
        e0 += __shfl_xor_sync(0xffffffffu, e0, o);
        e1 += __shfl_xor_sync(0xffffffffu, e1, o);
        e2 += __shfl_xor_sync(0xffffffffu, e2, o);
    }
    const float invZ = 1.0f / Z;

    // Direct sparse scatter (row already zeroed)
    float* rowp = out + PROBS_OFF + (size_t)(bN + i) * Nv;
    for (int p = lane; p < M; p += 32) rowp[s_idx[p]] = s_val[p] * invZ;

    if (lane == 0) {
        float Ex0 = e0 * invZ, Ex1 = e1 * invZ, Ex2 = e2 * invZ;
        float p0 = (float)(i >> 8) * step - 1.0f;
        float p1 = (float)((i >> 4) & 15) * step - 1.0f;
        float p2 = (float)(i & 15) * step - 1.0f;
        size_t ri = (size_t)(bN + i);
        out[EXP_OFF + ri * 3 + 0] = Ex0;
        out[EXP_OFF + ri * 3 + 1] = Ex1;
        out[EXP_OFF + ri * 3 + 2] = Ex2;
        out[DISP_OFF + (size_t)b * 3 * Nv + 0 * Nv + i] = Ex0 - p0;
        out[DISP_OFF + (size_t)b * 3 * Nv + 1 * Nv + i] = Ex1 - p1;
        out[DISP_OFF + (size_t)b * 3 * Nv + 2 * Nv + i] = Ex2 - p2;
        float l0 = src_ml[(size_t)b * 2 * Nv + i];
        float l1 = src_ml[(size_t)b * 2 * Nv + Nv + i];
        float smatch = 1.0f / (1.0f + __expf(l1 - l0));
        out[CONF_OFF + ri] = invZ * smatch;          // max prob == 1/Z exactly
        // ent = -sum p log p = logZ - (sum e*u)/Z   with u = (s - max)/T
        out[ENT_OFF + ri] = __logf(Z) - eu * invZ;
        out[SP_OFF + ri * 3 + 0] = p0;
        out[SP_OFF + ri * 3 + 1] = p1;
        out[SP_OFF + ri * 3 + 2] = p2;
    }
}

extern "C" void kernel_launch(void* const* d_in, const int* in_sizes, int n_in,
                              void* d_out, int out_size) {
    const float* src_can  = (const float*)d_in[0];
    const float* tgt_can  = (const float*)d_in[1];
    const float* src_desc = (const float*)d_in[2];
    const float* tgt_desc = (const float*)d_in[3];
    const float* src_ml   = (const float*)d_in[4];
    const float* tgt_ml   = (const float*)d_in[5];
    const float* src_unc  = (const float*)d_in[6];
    const float* tgt_unc  = (const float*)d_in[7];
    float* out = (float*)d_out;

    dim3 tgrid(Nv / 32, Cv / 32, Bv * 2);
    dim3 tblk(32, 8);
    transpose_kernel<<<tgrid, tblk>>>(tgt_desc, src_desc);
    prep_kernel<<<(Bv * Nv + 255) / 256, 256>>>(tgt_can, tgt_ml, tgt_unc);
    matcher_kernel<<<Bv * Nv, 256>>>(src_can, src_ml, src_unc, out);
}

// round 17
// speedup vs baseline: 2.9866x; 1.0049x over previous
#include <cuda_runtime.h>
#include <math.h>
#include <float.h>

#define Bv 2
#define Nv 4096
#define Cv 64
#define TOPKv 24
#define MAXM 512

// Output layout (concatenated, float32):
// expected (B,N,3) | disp (B,3,N) | probs (B,N,N) | conf (B,N) | ent (B,N) | src_pos (B,N,3)
#define EXP_OFF   ((size_t)0)
#define DISP_OFF  ((size_t)(Bv*Nv*3))
#define PROBS_OFF ((size_t)(2*Bv*Nv*3))
#define CONF_OFF  (PROBS_OFF + (size_t)Bv*Nv*Nv)
#define ENT_OFF   (CONF_OFF + (size_t)Bv*Nv)
#define SP_OFF    (ENT_OFF + (size_t)Bv*Nv)

// Scratch (no cudaMalloc allowed)
__device__ float4 g_pack[Bv*Nv];            // (x, y, z, ||t||^2) per target node
__device__ float  g_tdT[(size_t)Bv*Nv*Cv];  // tgt_desc transposed: (B,N,64)
__device__ float  g_sdT[(size_t)Bv*Nv*Cv];  // src_desc transposed: (B,N,64)
__device__ float  g_adj[Bv*Nv];             // max(log softmax(tml)[...,0], -20) - 0.1*tgt_unc

// Coalesced 32x32 tiled transpose: (B,64,N) -> (B,N,64) for both desc tensors
__global__ void transpose_kernel(const float* __restrict__ td,
                                 const float* __restrict__ sd) {
    __shared__ float tile[32][33];
    const int jb = blockIdx.x * 32;
    const int cb = blockIdx.y * 32;
    const int zz = blockIdx.z;
    const int b  = zz >> 1;
    const float* src = (zz & 1) ? sd : td;
    float* dst       = (zz & 1) ? g_sdT : g_tdT;
    const int tx = threadIdx.x, ty = threadIdx.y;   // 32 x 8
    const float* s = src + (size_t)b * Cv * Nv;
#pragma unroll
    for (int k = 0; k < 4; k++)
        tile[ty + k * 8][tx] = s[(size_t)(cb + ty + k * 8) * Nv + jb + tx];
    __syncthreads();
    float* d = dst + (size_t)b * Nv * 64;
#pragma unroll
    for (int k = 0; k < 4; k++)
        d[(size_t)(jb + ty + k * 8) * 64 + cb + tx] = tile[tx][ty + k * 8];
}

__global__ void prep_kernel(const float* __restrict__ tc,
                            const float* __restrict__ tml,
                            const float* __restrict__ tunc) {
    int idx = blockIdx.x * blockDim.x + threadIdx.x;
    if (idx < Bv * Nv) {
        int b = idx >> 12, j = idx & (Nv - 1);
        const float* t = tc + (size_t)b * 3 * Nv;
        float x = t[j], y = t[Nv + j], z = t[2 * Nv + j];
        g_pack[idx] = make_float4(x, y, z, x * x + y * y + z * z);
        float l0 = tml[(size_t)b * 2 * Nv + j];
        float l1 = tml[(size_t)b * 2 * Nv + Nv + j];
        g_adj[idx] = fmaxf(-log1pf(expf(l1 - l0)), -20.0f) - 0.1f * tunc[idx];
    }
}

__global__ void __launch_bounds__(256, 7)
matcher_kernel(const float* __restrict__ src_can,
               const float* __restrict__ src_ml,
               const float* __restrict__ src_unc,
               float* __restrict__ out) {
    __shared__ float s_d2[Nv];            // used only by the rare fallback
    __shared__ float s_sd[64];
    __shared__ int   s_idx[MAXM];
    __shared__ float s_d2a[MAXM];         // d2 per gathered pair
    __shared__ float s_val[MAXM];         // bin candidates / scores / exp
    __shared__ int   s_redi[8];
    __shared__ int   s_hist[256];         // fallback histogram
    __shared__ int   s_binB, s_kb, s_c2;
    __shared__ float s_tau;
    __shared__ int   s_cnt, s_cntR;

    const int tid  = threadIdx.x;
    const int lane = tid & 31;
    const int bi   = blockIdx.x;
    const int b    = bi >> 12;
    const int i    = bi & (Nv - 1);
    const int bN   = b * Nv;

    // Zero this row of probs output (coalesced; stores drain in background)
    float4* rowz = reinterpret_cast<float4*>(out + PROBS_OFF + (size_t)(bN + i) * Nv);
#pragma unroll
    for (int k = 0; k < 4; k++) rowz[tid + 256 * k] = make_float4(0.f, 0.f, 0.f, 0.f);

    if (tid < 16)
        reinterpret_cast<float4*>(s_sd)[tid] =
            reinterpret_cast<const float4*>(g_sdT + ((size_t)(bN + i) << 6))[tid];
    if (tid == 0) { s_cnt = 0; s_cntR = 0; }

    const float* sc = src_can + (size_t)b * 3 * Nv;
    const float sx = sc[i], sy = sc[Nv + i], sz = sc[2 * Nv + i];
    const float sn2 = sx * sx + sy * sy + sz * sz;

    const float4* __restrict__ pk = g_pack + bN;
    const float R2 = 0.45f * 0.45f;
    // Adaptive gather radius: targets ~48 hits from local Gaussian density,
    // capped; under/overshoot rows take the exact fallback below.
    const float Rp2 = fminf(2.25f, fmaxf(R2, R2 * 0.617f * __expf(sn2 * 0.33333334f)));

    __syncthreads();   // counters init visible before gather atomics

    // Pass 1: 4096 distances, pure LDG.128/FMA/cmp -> bitmask (NO smem stores)
    unsigned hm = 0;
#pragma unroll
    for (int k = 0; k < 16; k++) {
        int j = (k << 8) + tid;
        float4 t = pk[j];
        float dot = fmaf(sx, t.x, fmaf(sy, t.y, sz * t.z));
        float d2 = fmaf(-2.0f, dot, sn2 + t.w);
        if (d2 <= Rp2) hm |= (1u << k);
    }

    // Extraction: recompute d2 for hits only (g_pack is L1-hot), store (idx,d2),
    // and count true-radius hits.
    if (hm) {
        int base = atomicAdd(&s_cnt, __popc(hm));
        int cR = 0;
        while (hm) {
            int k = __ffs(hm) - 1;
            hm &= hm - 1;
            int j = (k << 8) + tid;
            float4 t = pk[j];
            float dot = fmaf(sx, t.x, fmaf(sy, t.y, sz * t.z));
            float d2 = fmaf(-2.0f, dot, sn2 + t.w);
            cR += (d2 <= R2) ? 1 : 0;
            if (base < MAXM) { s_idx[base] = j; s_d2a[base] = d2; }
            base++;
        }
        if (cR) atomicAdd(&s_cntR, cR);
    }
    __syncthreads();

    int Mp = s_cnt;
    float tauF;

    if (Mp >= TOPKv && Mp <= MAXM) {
        if (s_cntR >= TOPKv) {
            // fast: allowed = radius hits exactly (top-24 is a subset)
            tauF = R2;
        } else {
            // slow: allowed = top-24 (+ties); all top-24 are in the gathered
            // list since it holds >= 24 values <= Rp2. One-shot rank select.
            for (int p = tid; p < Mp; p += 256) {
                float x = fmaxf(s_d2a[p], 0.0f);
                int lt = 0, eq = 0;
                for (int q = 0; q < Mp; q++) {
                    float y = fmaxf(s_d2a[q], 0.0f);
                    lt += (y < x);
                    eq += (y == x);
                }
                if (lt <= TOPKv - 1 && TOPKv - 1 < lt + eq) s_tau = x;
            }
            __syncthreads();
            tauF = s_tau;          // > R2 here since cntR < TOPK
        }
    } else {
        // Fallback (~0.7% of rows): gather under/overshot. Full scan ->
        // exponent-histogram select (validated R15) -> rebuild list.
#pragma unroll
        for (int k = 0; k < 16; k++) {
            int j = (k << 8) + tid;
            float4 t = pk[j];
            float dot = fmaf(sx, t.x, fmaf(sy, t.y, sz * t.z));
            s_d2[j] = fmaf(-2.0f, dot, sn2 + t.w);
        }
        s_hist[tid] = 0;
        __syncthreads();
#pragma unroll
        for (int k = 0; k < 16; k++) {
            unsigned bits = __float_as_uint(fmaxf(s_d2[(k << 8) + tid], 0.0f));
            atomicAdd(&s_hist[bits >> 23], 1);
        }
        __syncthreads();
        int v = s_hist[tid];
        int cum = v;
#pragma unroll
        for (int o = 1; o < 32; o <<= 1) {
            int t = __shfl_up_sync(0xffffffffu, cum, o);
            if (lane >= o) cum += t;
        }
        if (lane == 31) s_redi[tid >> 5] = cum;
        __syncthreads();
        int off = 0;
        for (int w = 0; w < (tid >> 5); w++) off += s_redi[w];
        cum += off;
        if (cum >= TOPKv && cum - v < TOPKv) { s_binB = tid; s_kb = cum - v; }
        if (tid == 0) s_c2 = 0;
        __syncthreads();
        const int B = s_binB;
        const int r = TOPKv - s_kb;
#pragma unroll
        for (int k = 0; k < 16; k++) {
            float key = fmaxf(s_d2[(k << 8) + tid], 0.0f);
            if ((int)(__float_as_uint(key) >> 23) == B) {
                int p = atomicAdd(&s_c2, 1);
                if (p < MAXM) s_val[p] = key;
            }
        }
        __syncthreads();
        int c2 = min(s_c2, MAXM);
        for (int p = tid; p < c2; p += 256) {
            float x = s_val[p];
            int lt = 0, eq = 0;
            for (int q = 0; q < c2; q++) {
                float y = s_val[q];
                lt += (y < x);
                eq += (y == x);
            }
            if (lt <= r - 1 && r - 1 < lt + eq) s_tau = x;
        }
        __syncthreads();
        tauF = fmaxf(s_tau, R2);   // allowed <=> clamped d2 <= max(tau24, R2)
        if (tid == 0) s_cnt = 0;
        __syncthreads();
#pragma unroll
        for (int k = 0; k < 16; k++) {
            int j = (k << 8) + tid;
            float d2 = s_d2[j];
            if (fmaxf(d2, 0.0f) <= tauF) {
                int p = atomicAdd(&s_cnt, 1);
                if (p < MAXM) { s_idx[p] = j; s_d2a[p] = d2; }
            }
        }
        __syncthreads();
        Mp = s_cnt;
    }
    const int M = min(Mp, MAXM);

    // Scores: half-warp (16 lanes) per pair, float4 loads, 4 shuffles/pair.
    // Pairs beyond tauF get a sentinel (they were gathered but not allowed).
    const float sunc = src_unc[bN + i];
    {
        const int half = tid >> 4;
        const int hl   = tid & 15;
        const float4 sd4 = reinterpret_cast<const float4*>(s_sd)[hl];
        const int T = (M + 15) >> 4;
        for (int t = 0; t < T; t++) {
            int p = (t << 4) + half;
            float part = 0.0f;
            int j = 0;
            if (p < M) {
                j = s_idx[p];
                float4 v = reinterpret_cast<const float4*>(
                               g_tdT + ((size_t)(bN + j) << 6))[hl];
                part = fmaf(v.x, sd4.x, fmaf(v.y, sd4.y,
                       fmaf(v.z, sd4.z, v.w * sd4.w)));
            }
#pragma unroll
            for (int o = 8; o; o >>= 1)
                part += __shfl_xor_sync(0xffffffffu, part, o, 16);
            if (hl == 0 && p < M) {
                float key = s_d2a[p];
                if (fmaxf(key, 0.0f) <= tauF) {
                    float dist = sqrtf(fmaxf(key, 1e-12f));
                    s_val[p] = part - dist - 0.1f * sunc + g_adj[bN + j];
                } else {
                    s_val[p] = -1e30f;   // excluded: contributes e=0 below
                }
            }
        }
    }
    __syncthreads();   // s_val/s_idx complete and visible

    // Warp-specialized tail: warps 1..7 exit; warp 0 owns softmax + outputs.
    if (tid >= 32) return;

    float lm = -FLT_MAX;
    for (int p = lane; p < M; p += 32) lm = fmaxf(lm, s_val[p]);
#pragma unroll
    for (int o = 16; o; o >>= 1) lm = fmaxf(lm, __shfl_xor_sync(0xffffffffu, lm, o));
    const float mx = lm;

    const float invT = 1.0f / 0.07f;
    const float step = 2.0f / 15.0f;
    float Z = 0.f, eu = 0.f, e0 = 0.f, e1 = 0.f, e2 = 0.f;
    for (int p = lane; p < M; p += 32) {
        float sv = s_val[p];
        bool ok = sv > -1e29f;
        float u = ok ? (sv - mx) * invT : -40.0f;
        float e = ok ? __expf(u) : 0.0f;
        s_val[p] = e;
        Z += e; eu += e * u;
        int j = s_idx[p];
        float c0 = (float)(j >> 8) * step - 1.0f;
        float c1 = (float)((j >> 4) & 15) * step - 1.0f;
        float c2 = (float)(j & 15) * step - 1.0f;
        e0 += e * c0; e1 += e * c1; e2 += e * c2;
    }
#pragma unroll
    for (int o = 16; o; o >>= 1) {
        Z  += __shfl_xor_sync(0xffffffffu, Z, o);
        eu += __shfl_xor_sync(0xffffffffu, eu, o);
        e0 += __shfl_xor_sync(0xffffffffu, e0, o);
        e1 += __shfl_xor_sync(0xffffffffu, e1, o);
        e2 += __shfl_xor_sync(0xffffffffu, e2, o);
    }
    const float invZ = 1.0f / Z;

    // Scatter: excluded pairs write 0 over an already-zero row (harmless)
    float* rowp = out + PROBS_OFF + (size_t)(bN + i) * Nv;
    for (int p = lane; p < M; p += 32) rowp[s_idx[p]] = s_val[p] * invZ;

    if (lane == 0) {
        float Ex0 = e0 * invZ, Ex1 = e1 * invZ, Ex2 = e2 * invZ;
        float p0 = (float)(i >> 8) * step - 1.0f;
        float p1 = (float)((i >> 4) & 15) * step - 1.0f;
        float p2 = (float)(i & 15) * step - 1.0f;
        size_t ri = (size_t)(bN + i);
        out[EXP_OFF + ri * 3 + 0] = Ex0;
        out[EXP_OFF + ri * 3 + 1] = Ex1;
        out[EXP_OFF + ri * 3 + 2] = Ex2;
        out[DISP_OFF + (size_t)b * 3 * Nv + 0 * Nv + i] = Ex0 - p0;
        out[DISP_OFF + (size_t)b * 3 * Nv + 1 * Nv + i] = Ex1 - p1;
        out[DISP_OFF + (size_t)b * 3 * Nv + 2 * Nv + i] = Ex2 - p2;
        float l0 = src_ml[(size_t)b * 2 * Nv + i];
        float l1 = src_ml[(size_t)b * 2 * Nv + Nv + i];
        float smatch = 1.0f / (1.0f + __expf(l1 - l0));
        out[CONF_OFF + ri] = invZ * smatch;          // max prob == 1/Z exactly
        out[ENT_OFF + ri] = __logf(Z) - eu * invZ;
        out[SP_OFF + ri * 3 + 0] = p0;
        out[SP_OFF + ri * 3 + 1] = p1;
        out[SP_OFF + ri * 3 + 2] = p2;
    }
}

extern "C" void kernel_launch(void* const* d_in, const int* in_sizes, int n_in,
                              void* d_out, int out_size) {
    const float* src_can  = (const float*)d_in[0];
    const float* tgt_can  = (const float*)d_in[1];
    const float* src_desc = (const float*)d_in[2];
    const float* tgt_desc = (const float*)d_in[3];
    const float* src_ml   = (const float*)d_in[4];
    const float* tgt_ml   = (const float*)d_in[5];
    const float* src_unc  = (const float*)d_in[6];
    const float* tgt_unc  = (const float*)d_in[7];
    float* out = (float*)d_out;

    dim3 tgrid(Nv / 32, Cv / 32, Bv * 2);
    dim3 tblk(32, 8);
    transpose_kernel<<<tgrid, tblk>>>(tgt_desc, src_desc);
    prep_kernel<<<(Bv * Nv + 255) / 256, 256>>>(tgt_can, tgt_ml, tgt_unc);
    matcher_kernel<<<Bv * Nv, 256>>>(src_can, src_ml, src_unc, out);
}